// round 7
// baseline (speedup 1.0000x reference)
#include <cuda_runtime.h>
#include <math.h>

// ---------------- problem constants ----------------
#define NB    64        // batch
#define NN    1000      // nodes per sample
#define NTOT  64000     // NB*NN
#define SEQL  12
#define INCH  48
#define D1    4000      // NN*FEAT
#define H1S   256
#define H2S   128
#define G1    1024      // 4*H1S
#define G2    512       // 4*H2S
#define TBR   768       // SEQL*NB
#define EMAX  1024000
#define ETOTMAX (EMAX + NTOT)

// ---------------- scratch (device globals; no allocation allowed) ----------------
__device__ __align__(256) float d_h[NTOT * 96];        // GAT hidden, [n][head][c]
__device__ __align__(256) float d_asrc[NTOT * 2];
__device__ __align__(256) float d_adst[NTOT * 2];
__device__ __align__(256) float d_m[NTOT * 2];         // segment max
__device__ __align__(256) float d_den[NTOT * 2];       // segment sum
__device__ __align__(256) float d_w[ETOTMAX * 2];      // edge softmax weights -> alpha
__device__ __align__(256) float d_g[NTOT * 48];        // GAT output (head-mean, no bias)
__device__ __align__(256) float d_xin[TBR * D1];       // LSTM1 input, row = t*NB+b
__device__ __align__(256) float d_xw1[TBR * G1];
__device__ __align__(256) float d_y1[TBR * H1S];
__device__ __align__(256) float d_xw2[TBR * G2];
__device__ __align__(256) float d_gates[NB * G1];
__device__ __align__(256) float d_h1[NB * H1S];
__device__ __align__(256) float d_c1[NB * H1S];
__device__ __align__(256) float d_h2[NB * H2S];
__device__ __align__(256) float d_c2[NB * H2S];
__device__ __align__(256) float d_whh1T[H1S * G1];
__device__ __align__(256) float d_whh2T[H2S * G2];

// ---------------- helpers ----------------
__device__ __forceinline__ float sigf(float x) { return 1.f / (1.f + expf(-x)); }

// float atomic max: int-max for >=0, uint-min for <0 (works mixed-sign, init -inf)
__device__ __forceinline__ void atomicMaxF(float* addr, float v) {
    if (v >= 0.f) atomicMax((int*)addr, __float_as_int(v));
    else          atomicMin((unsigned int*)addr, __float_as_uint(v));
}

// ---------------- kernels ----------------
__global__ void k_init() {
    int idx = blockIdx.x * blockDim.x + threadIdx.x;
    if (idx < NTOT * 48) d_g[idx] = 0.f;
    if (idx < NTOT * 2) { d_m[idx] = __int_as_float(0xff800000); d_den[idx] = 0.f; }
    if (idx < NB * H1S) { d_h1[idx] = 0.f; d_c1[idx] = 0.f; }
    if (idx < NB * H2S) { d_h2[idx] = 0.f; d_c2[idx] = 0.f; }
}

// h[n, j] = sum_k x[n,k] * Wg[k, j]   (Wg: [48][96] row-major, cached in smem)
__global__ void k_gemm_h(const float* __restrict__ x, const float* __restrict__ Wg) {
    __shared__ float ws[48 * 96];
    for (int i = threadIdx.x; i < 48 * 96; i += blockDim.x) ws[i] = Wg[i];
    __syncthreads();
    int idx = blockIdx.x * blockDim.x + threadIdx.x;
    if (idx >= NTOT * 96) return;
    int n = idx / 96, j = idx % 96;
    const float* xr = x + (size_t)n * 48;
    float acc = 0.f;
#pragma unroll
    for (int k = 0; k < 48; k++) acc = fmaf(__ldg(xr + k), ws[k * 96 + j], acc);
    d_h[idx] = acc;
}

// a_src[n,h] / a_dst[n,h]
__global__ void k_attn(const float* __restrict__ att_s, const float* __restrict__ att_d) {
    int idx = blockIdx.x * blockDim.x + threadIdx.x;
    if (idx >= NTOT * 2) return;
    int n = idx >> 1, hd = idx & 1;
    const float* hr = d_h + (size_t)n * 96 + hd * 48;
    float s1 = 0.f, s2 = 0.f;
#pragma unroll
    for (int c = 0; c < 48; c++) {
        float hv = hr[c];
        s1 = fmaf(hv, __ldg(att_s + hd * 48 + c), s1);
        s2 = fmaf(hv, __ldg(att_d + hd * 48 + c), s2);
    }
    d_asrc[idx] = s1;
    d_adst[idx] = s2;
}

// edge_index arrives as int32 (JAX x64 is disabled; "int64" arrays are int32 on device)
__device__ __forceinline__ void edge_sd(const int* __restrict__ ei, int E, int e,
                                        int& s, int& d) {
    if (e < E) { s = ei[e]; d = ei[E + e]; }
    else       { s = e - E; d = s; }
}

__global__ void k_passA(const int* __restrict__ ei, int E) {
    int idx = blockIdx.x * blockDim.x + threadIdx.x;
    int etot = E + NTOT;
    if (idx >= etot * 2) return;
    int e = idx >> 1, hd = idx & 1;
    int s, d; edge_sd(ei, E, e, s, d);
    float v = d_asrc[s * 2 + hd] + d_adst[d * 2 + hd];
    v = v > 0.f ? v : 0.2f * v;            // leaky_relu(., 0.2)
    atomicMaxF(&d_m[d * 2 + hd], v);
}

__global__ void k_passB(const int* __restrict__ ei, int E) {
    int idx = blockIdx.x * blockDim.x + threadIdx.x;
    int etot = E + NTOT;
    if (idx >= etot * 2) return;
    int e = idx >> 1, hd = idx & 1;
    int s, d; edge_sd(ei, E, e, s, d);
    float v = d_asrc[s * 2 + hd] + d_adst[d * 2 + hd];
    v = v > 0.f ? v : 0.2f * v;
    float w = expf(v - d_m[d * 2 + hd]);
    d_w[idx] = w;
    atomicAdd(&d_den[d * 2 + hd], w);
}

// alpha = w / (den+eps) * 0.5 (0.5 = head-mean folded in)
__global__ void k_alpha(const int* __restrict__ ei, int E) {
    int idx = blockIdx.x * blockDim.x + threadIdx.x;
    int etot = E + NTOT;
    if (idx >= etot * 2) return;
    int e = idx >> 1, hd = idx & 1;
    int s, d; edge_sd(ei, E, e, s, d);
    d_w[idx] = d_w[idx] / (d_den[d * 2 + hd] + 1e-16f) * 0.5f;
}

// g[dst, c] += alpha0*h[src,0,c] + alpha1*h[src,1,c]
__global__ void k_passC(const int* __restrict__ ei, int E) {
    int idx = blockIdx.x * blockDim.x + threadIdx.x;
    int etot = E + NTOT;
    if (idx >= etot * 48) return;
    int e = idx / 48, c = idx % 48;
    int s, d; edge_sd(ei, E, e, s, d);
    float a0 = d_w[e * 2 + 0];
    float a1 = d_w[e * 2 + 1];
    float v = a0 * d_h[(size_t)s * 96 + c] + a1 * d_h[(size_t)s * 96 + 48 + c];
    atomicAdd(&d_g[(size_t)d * 48 + c], v);
}

// x_seq[t, b, n*4+f] = g[(b*NN+n), t*4+f] + bias[t*4+f]
__global__ void k_reshape(const float* __restrict__ gbias) {
    int idx = blockIdx.x * blockDim.x + threadIdx.x;
    if (idx >= TBR * D1) return;
    int dd = idx % D1;
    int tb = idx / D1;
    int b = tb % NB;
    int t = tb / NB;
    int n = dd >> 2, f = dd & 3;
    int c = (t << 2) + f;
    d_xin[idx] = d_g[(size_t)(b * NN + n) * 48 + c] + __ldg(gbias + c);
}

// NT SGEMM: C[m,n] = sum_k A[m,k]*B[n,k] + bias[n].
// sel==1: A=d_xin (lda=D1), C=d_xw1 ; sel==2: A=d_y1 (lda=H1S), C=d_xw2
// Tile 64x64, GK=16, 128 threads, 4x8 microtile. M=TBR, N%64==0, K%16==0.
__global__ void k_sgemm(int sel, const float* __restrict__ B,
                        const float* __restrict__ bias, int N, int K, int ldb) {
    const float* A = (sel == 1) ? d_xin : d_y1;
    float* C       = (sel == 1) ? d_xw1 : d_xw2;
    int lda        = (sel == 1) ? D1 : H1S;

    __shared__ __align__(16) float As[16][64];
    __shared__ __align__(16) float Bs[16][64];
    int t = threadIdx.x;          // 0..127
    int ty = t >> 3;              // 0..15 -> rows
    int tx = t & 7;               // 0..7  -> cols
    int m0 = blockIdx.y * 64;
    int n0 = blockIdx.x * 64;

    float acc[4][8];
#pragma unroll
    for (int i = 0; i < 4; i++)
#pragma unroll
        for (int j = 0; j < 8; j++) acc[i][j] = 0.f;

    for (int k0 = 0; k0 < K; k0 += 16) {
#pragma unroll
        for (int l = 0; l < 2; l++) {
            int lin = t + l * 128;        // 0..255
            int mm = lin & 63;
            int kk4 = lin >> 6;           // 0..3
            float4 av = *(const float4*)(A + (size_t)(m0 + mm) * lda + k0 + kk4 * 4);
            As[kk4 * 4 + 0][mm] = av.x; As[kk4 * 4 + 1][mm] = av.y;
            As[kk4 * 4 + 2][mm] = av.z; As[kk4 * 4 + 3][mm] = av.w;
            float4 bv = *(const float4*)(B + (size_t)(n0 + mm) * ldb + k0 + kk4 * 4);
            Bs[kk4 * 4 + 0][mm] = bv.x; Bs[kk4 * 4 + 1][mm] = bv.y;
            Bs[kk4 * 4 + 2][mm] = bv.z; Bs[kk4 * 4 + 3][mm] = bv.w;
        }
        __syncthreads();
#pragma unroll
        for (int kk = 0; kk < 16; kk++) {
            float4 a  = *(const float4*)&As[kk][ty * 4];
            float4 b0 = *(const float4*)&Bs[kk][tx * 8];
            float4 b1 = *(const float4*)&Bs[kk][tx * 8 + 4];
            float av[4] = {a.x, a.y, a.z, a.w};
            float bv[8] = {b0.x, b0.y, b0.z, b0.w, b1.x, b1.y, b1.z, b1.w};
#pragma unroll
            for (int i = 0; i < 4; i++)
#pragma unroll
                for (int j = 0; j < 8; j++) acc[i][j] = fmaf(av[i], bv[j], acc[i][j]);
        }
        __syncthreads();
    }
#pragma unroll
    for (int i = 0; i < 4; i++) {
        int m = m0 + ty * 4 + i;
        float* cr = C + (size_t)m * N + n0 + tx * 8;
        const float* br = bias + n0 + tx * 8;
#pragma unroll
        for (int j = 0; j < 8; j++) cr[j] = acc[i][j] + __ldg(br + j);
    }
}

// WT[k*G + j] = W[j*Hs + k]
__global__ void k_transpose(int which, const float* __restrict__ W) {
    int G  = (which == 1) ? G1 : G2;
    int Hs = (which == 1) ? H1S : H2S;
    float* WT = (which == 1) ? d_whh1T : d_whh2T;
    int idx = blockIdx.x * blockDim.x + threadIdx.x;
    if (idx >= G * Hs) return;
    int k = idx / G, j = idx % G;
    WT[idx] = W[(size_t)j * Hs + k];
}

// gates[b, j] = xw[t*NB+b, j] + sum_k h[b,k] * WT[k, j]
// grid: (G/128, NB/8), block 128. Each thread: 8 batches.
__global__ void k_lstm_step(int which, int t) {
    const float* xw = (which == 1) ? d_xw1 : d_xw2;
    const float* WT = (which == 1) ? d_whh1T : d_whh2T;
    const float* hs = (which == 1) ? d_h1 : d_h2;
    int G  = (which == 1) ? G1 : G2;
    int Hs = (which == 1) ? H1S : H2S;

    __shared__ __align__(16) float hl[8 * H1S];   // [k][b] transposed
    int b0 = blockIdx.y * 8;
    for (int i = threadIdx.x; i < 8 * Hs; i += blockDim.x) {
        int k = i >> 3, b = i & 7;
        hl[i] = hs[(size_t)(b0 + b) * Hs + k];
    }
    __syncthreads();

    int j = blockIdx.x * blockDim.x + threadIdx.x;
    float acc[8];
#pragma unroll
    for (int b = 0; b < 8; b++) acc[b] = 0.f;

    for (int k = 0; k < Hs; k++) {
        float w = __ldg(WT + (size_t)k * G + j);
        float4 hA = *(const float4*)(hl + k * 8);
        float4 hB = *(const float4*)(hl + k * 8 + 4);
        acc[0] = fmaf(w, hA.x, acc[0]); acc[1] = fmaf(w, hA.y, acc[1]);
        acc[2] = fmaf(w, hA.z, acc[2]); acc[3] = fmaf(w, hA.w, acc[3]);
        acc[4] = fmaf(w, hB.x, acc[4]); acc[5] = fmaf(w, hB.y, acc[5]);
        acc[6] = fmaf(w, hB.z, acc[6]); acc[7] = fmaf(w, hB.w, acc[7]);
    }
#pragma unroll
    for (int b = 0; b < 8; b++) {
        d_gates[(size_t)(b0 + b) * G + j] =
            acc[b] + __ldg(xw + ((size_t)t * NB + b0 + b) * G + j);
    }
}

// PyTorch gate order (i,f,g,o)
__global__ void k_lstm_elem(int which, int t) {
    int Hs = (which == 1) ? H1S : H2S;
    int G = 4 * Hs;
    float* hs = (which == 1) ? d_h1 : d_h2;
    float* cs = (which == 1) ? d_c1 : d_c2;
    int idx = blockIdx.x * blockDim.x + threadIdx.x;
    if (idx >= NB * Hs) return;
    int b = idx / Hs, u = idx % Hs;
    const float* gr = d_gates + (size_t)b * G;
    float iv = sigf(gr[u]);
    float fv = sigf(gr[Hs + u]);
    float gv = tanhf(gr[2 * Hs + u]);
    float ov = sigf(gr[3 * Hs + u]);
    float c = fv * cs[idx] + iv * gv;
    float h = ov * tanhf(c);
    cs[idx] = c;
    hs[idx] = h;
    if (which == 1) d_y1[(size_t)t * NB * H1S + idx] = h;
}

// out[b*2000 + j] = sum_k h2[b,k] * W_out[j,k] + b_out[j]
__global__ void k_out(const float* __restrict__ Wo, const float* __restrict__ bo,
                      float* __restrict__ out) {
    __shared__ float hr[H2S];
    int b = blockIdx.y;
    if (threadIdx.x < H2S) hr[threadIdx.x] = d_h2[(size_t)b * H2S + threadIdx.x];
    __syncthreads();
    int j = blockIdx.x * blockDim.x + threadIdx.x;
    if (j >= NN * 2) return;
    const float* wr = Wo + (size_t)j * H2S;
    float acc = 0.f;
#pragma unroll 4
    for (int k = 0; k < H2S; k++) acc = fmaf(hr[k], __ldg(wr + k), acc);
    out[(size_t)b * (NN * 2) + j] = acc + __ldg(bo + j);
}

// ---------------- launch ----------------
extern "C" void kernel_launch(void* const* d_in, const int* in_sizes, int n_in,
                              void* d_out, int out_size) {
    const float* x     = (const float*)d_in[0];
    const int*   ei    = (const int*)d_in[1];     // int32 (JAX x64 disabled)
    const float* Wg    = (const float*)d_in[2];
    const float* att_s = (const float*)d_in[3];
    const float* att_d = (const float*)d_in[4];
    const float* gbias = (const float*)d_in[5];
    const float* Wih1  = (const float*)d_in[6];
    const float* Whh1  = (const float*)d_in[7];
    const float* b1    = (const float*)d_in[8];
    const float* Wih2  = (const float*)d_in[9];
    const float* Whh2  = (const float*)d_in[10];
    const float* b2    = (const float*)d_in[11];
    const float* Wo    = (const float*)d_in[12];
    const float* bo    = (const float*)d_in[13];
    float* out = (float*)d_out;

    int E = in_sizes[1] / 2;
    if (E > EMAX) E = EMAX;
    int etot = E + NTOT;

    k_init<<<(NTOT * 48 + 255) / 256, 256>>>();
    k_gemm_h<<<(NTOT * 96 + 255) / 256, 256>>>(x, Wg);
    k_transpose<<<(H1S * G1 + 255) / 256, 256>>>(1, Whh1);
    k_transpose<<<(H2S * G2 + 255) / 256, 256>>>(2, Whh2);
    k_attn<<<(NTOT * 2 + 255) / 256, 256>>>(att_s, att_d);
    k_passA<<<(etot * 2 + 255) / 256, 256>>>(ei, E);
    k_passB<<<(etot * 2 + 255) / 256, 256>>>(ei, E);
    k_alpha<<<(etot * 2 + 255) / 256, 256>>>(ei, E);
    k_passC<<<(etot * 48 + 255) / 256, 256>>>(ei, E);
    k_reshape<<<(TBR * D1 + 255) / 256, 256>>>(gbias);

    k_sgemm<<<dim3(G1 / 64, TBR / 64), 128>>>(1, Wih1, b1, G1, D1, D1);
    for (int t = 0; t < SEQL; t++) {
        k_lstm_step<<<dim3(G1 / 128, NB / 8), 128>>>(1, t);
        k_lstm_elem<<<(NB * H1S + 255) / 256, 256>>>(1, t);
    }

    k_sgemm<<<dim3(G2 / 64, TBR / 64), 128>>>(2, Wih2, b2, G2, H1S, H1S);
    for (int t = 0; t < SEQL; t++) {
        k_lstm_step<<<dim3(G2 / 128, NB / 8), 128>>>(2, t);
        k_lstm_elem<<<(NB * H2S + 255) / 256, 256>>>(2, t);
    }

    k_out<<<dim3((NN * 2 + 255) / 256, NB), 256>>>(Wo, bo, out);
}

// round 9
// speedup vs baseline: 1.3125x; 1.3125x over previous
#include <cuda_runtime.h>
#include <math.h>

// ---------------- problem constants ----------------
#define NB    64        // batch
#define NN    1000      // nodes per sample
#define NTOT  64000     // NB*NN
#define SEQL  12
#define INCH  48
#define D1    4000      // NN*FEAT
#define H1S   256
#define H2S   128
#define G1    1024      // 4*H1S
#define G2    512       // 4*H2S
#define TBR   768       // SEQL*NB
#define EMAX  1024000
#define ETOTMAX (EMAX + NTOT)
#define SPLITK 5        // K=4000 -> klen=800, multiple of 16 (R8 fix: 4 gave klen=1000)

typedef unsigned long long ull;

// ---------------- scratch (device globals; no allocation allowed) ----------------
__device__ __align__(256) float d_h[NTOT * 96];        // GAT hidden, [n][head][c]
__device__ __align__(256) float d_asrc[NTOT * 2];
__device__ __align__(256) float d_adst[NTOT * 2];
__device__ __align__(256) float d_m[NTOT * 2];         // segment max
__device__ __align__(256) float d_den[NTOT * 2];       // segment sum
__device__ __align__(256) float d_w[ETOTMAX * 2];      // edge softmax weights -> alpha
__device__ __align__(256) float d_g[NTOT * 48];        // GAT output (head-mean, no bias)
__device__ __align__(256) float d_xin[TBR * D1];       // LSTM1 input, row = t*NB+b
__device__ __align__(256) float d_xw1[TBR * G1];
__device__ __align__(256) float d_y1[TBR * H1S];
__device__ __align__(256) float d_xw2[TBR * G2];
__device__ __align__(256) float d_gates[NB * G1];
__device__ __align__(256) float d_h1[NB * H1S];
__device__ __align__(256) float d_c1[NB * H1S];
__device__ __align__(256) float d_h2[NB * H2S];
__device__ __align__(256) float d_c2[NB * H2S];
__device__ __align__(256) float d_whh1T[H1S * G1];
__device__ __align__(256) float d_whh2T[H2S * G2];

// ---------------- helpers ----------------
__device__ __forceinline__ float sigf(float x) { return 1.f / (1.f + expf(-x)); }

__device__ __forceinline__ void atomicMaxF(float* addr, float v) {
    if (v >= 0.f) atomicMax((int*)addr, __float_as_int(v));
    else          atomicMin((unsigned int*)addr, __float_as_uint(v));
}

// packed f32x2 FMA (FFMA2): 2 fp32 FMAs per instruction, fma-pipe
__device__ __forceinline__ void fma2(ull& acc, ull a, ull b) {
    asm("fma.rn.f32x2 %0, %1, %2, %0;" : "+l"(acc) : "l"(a), "l"(b));
}
__device__ __forceinline__ ull pack2(float x, float y) {
    ull r; asm("mov.b64 %0, {%1, %2};" : "=l"(r) : "f"(x), "f"(y)); return r;
}
__device__ __forceinline__ float2 unpack2(ull v) {
    float2 r; asm("mov.b64 {%0, %1}, %2;" : "=f"(r.x), "=f"(r.y) : "l"(v)); return r;
}
__device__ __forceinline__ void redv4(float* dst, float a, float b, float c, float d) {
    asm volatile("red.global.add.v4.f32 [%0], {%1, %2, %3, %4};"
                 :: "l"(dst), "f"(a), "f"(b), "f"(c), "f"(d) : "memory");
}

// ---------------- kernels ----------------
__global__ void k_init() {
    int idx = blockIdx.x * blockDim.x + threadIdx.x;
    if (idx < NTOT * 48) d_g[idx] = 0.f;
    if (idx < NTOT * 2) { d_m[idx] = __int_as_float(0xff800000); d_den[idx] = 0.f; }
    if (idx < NB * H1S) { d_h1[idx] = 0.f; d_c1[idx] = 0.f; }
    if (idx < NB * H2S) { d_h2[idx] = 0.f; d_c2[idx] = 0.f; }
}

// d_xw1[m, j] = b1[j]  (bias pre-broadcast for split-K red output)
__global__ void k_biasinit(const float* __restrict__ b) {
    int idx = blockIdx.x * blockDim.x + threadIdx.x;
    if (idx >= TBR * G1) return;
    d_xw1[idx] = __ldg(b + (idx & (G1 - 1)));
}

// h[n, j2:j2+2] = sum_k x[n,k] * Wg[k, j2:j2+2]   (f32x2)
__global__ void k_gemm_h(const float* __restrict__ x, const float* __restrict__ Wg) {
    __shared__ __align__(16) float ws[48 * 96];
    for (int i = threadIdx.x; i < 48 * 96; i += blockDim.x) ws[i] = Wg[i];
    __syncthreads();
    int idx = blockIdx.x * blockDim.x + threadIdx.x;
    if (idx >= NTOT * 48) return;
    int n = idx / 48, j2 = (idx % 48) * 2;
    const float* xr = x + (size_t)n * 48;
    ull acc = 0;
#pragma unroll
    for (int k = 0; k < 48; k++) {
        float xv = __ldg(xr + k);
        fma2(acc, pack2(xv, xv), *(const ull*)(ws + k * 96 + j2));
    }
    float2 u = unpack2(acc);
    *(float2*)(d_h + (size_t)n * 96 + j2) = u;
}

__global__ void k_attn(const float* __restrict__ att_s, const float* __restrict__ att_d) {
    int idx = blockIdx.x * blockDim.x + threadIdx.x;
    if (idx >= NTOT * 2) return;
    int n = idx >> 1, hd = idx & 1;
    const float* hr = d_h + (size_t)n * 96 + hd * 48;
    float s1 = 0.f, s2 = 0.f;
#pragma unroll
    for (int c = 0; c < 48; c++) {
        float hv = hr[c];
        s1 = fmaf(hv, __ldg(att_s + hd * 48 + c), s1);
        s2 = fmaf(hv, __ldg(att_d + hd * 48 + c), s2);
    }
    d_asrc[idx] = s1;
    d_adst[idx] = s2;
}

// edge_index arrives as int32 (JAX x64 disabled)
__device__ __forceinline__ void edge_sd(const int* __restrict__ ei, int E, int e,
                                        int& s, int& d) {
    if (e < E) { s = ei[e]; d = ei[E + e]; }
    else       { s = e - E; d = s; }
}

__global__ void k_passA(const int* __restrict__ ei, int E) {
    int idx = blockIdx.x * blockDim.x + threadIdx.x;
    int etot = E + NTOT;
    if (idx >= etot * 2) return;
    int e = idx >> 1, hd = idx & 1;
    int s, d; edge_sd(ei, E, e, s, d);
    float v = d_asrc[s * 2 + hd] + d_adst[d * 2 + hd];
    v = v > 0.f ? v : 0.2f * v;
    atomicMaxF(&d_m[d * 2 + hd], v);
}

__global__ void k_passB(const int* __restrict__ ei, int E) {
    int idx = blockIdx.x * blockDim.x + threadIdx.x;
    int etot = E + NTOT;
    if (idx >= etot * 2) return;
    int e = idx >> 1, hd = idx & 1;
    int s, d; edge_sd(ei, E, e, s, d);
    float v = d_asrc[s * 2 + hd] + d_adst[d * 2 + hd];
    v = v > 0.f ? v : 0.2f * v;
    float w = expf(v - d_m[d * 2 + hd]);
    d_w[idx] = w;
    atomicAdd(&d_den[d * 2 + hd], w);
}

// alpha = w / (den+eps) * 0.5 (0.5 = head-mean folded in)
__global__ void k_alpha(const int* __restrict__ ei, int E) {
    int idx = blockIdx.x * blockDim.x + threadIdx.x;
    int etot = E + NTOT;
    if (idx >= etot * 2) return;
    int e = idx >> 1, hd = idx & 1;
    int s, d; edge_sd(ei, E, e, s, d);
    d_w[idx] = d_w[idx] / (d_den[d * 2 + hd] + 1e-16f) * 0.5f;
}

// g[dst, q*4:+4] += a0*h[src,0,q*4:+4] + a1*h[src,1,q*4:+4]  (vector red)
__global__ void k_passC(const int* __restrict__ ei, int E) {
    int idx = blockIdx.x * blockDim.x + threadIdx.x;
    int etot = E + NTOT;
    if (idx >= etot * 12) return;
    int e = idx / 12, q = idx - e * 12;
    int s, d; edge_sd(ei, E, e, s, d);
    float2 a = *(const float2*)(d_w + (size_t)e * 2);
    const float4 h0 = *(const float4*)(d_h + (size_t)s * 96 + q * 4);
    const float4 h1 = *(const float4*)(d_h + (size_t)s * 96 + 48 + q * 4);
    float vx = fmaf(a.x, h0.x, a.y * h1.x);
    float vy = fmaf(a.x, h0.y, a.y * h1.y);
    float vz = fmaf(a.x, h0.z, a.y * h1.z);
    float vw = fmaf(a.x, h0.w, a.y * h1.w);
    redv4(d_g + (size_t)d * 48 + q * 4, vx, vy, vz, vw);
}

// x_seq[t, b, n*4+f] = g[(b*NN+n), t*4+f] + bias[t*4+f]
__global__ void k_reshape(const float* __restrict__ gbias) {
    int idx = blockIdx.x * blockDim.x + threadIdx.x;
    if (idx >= TBR * D1) return;
    int dd = idx % D1;
    int tb = idx / D1;
    int b = tb % NB;
    int t = tb / NB;
    int n = dd >> 2, f = dd & 3;
    int c = (t << 2) + f;
    d_xin[idx] = d_g[(size_t)(b * NN + n) * 48 + c] + __ldg(gbias + c);
}

// NT SGEMM with f32x2: C[m,n] = sum_k A[m,k]*B[n,k] (+bias).
// sel==1: A=d_xin, C=d_xw1 (pre-init'd with bias), split-K via blockIdx.z, red-v4 output
// sel==2: A=d_y1,  C=d_xw2, single pass, bias added at store
// Tile 64x64, 128 threads, 4x8 per thread (as 4x4 f32x2 pairs). lda=ldb=K.
// REQUIREMENT: (K / kslices) % 16 == 0.
__global__ void k_sgemm(int sel, const float* __restrict__ B,
                        const float* __restrict__ bias, int N, int K) {
    const float* A = (sel == 1) ? d_xin : d_y1;
    float* C       = (sel == 1) ? d_xw1 : d_xw2;

    __shared__ __align__(16) float As[16][64];
    __shared__ __align__(16) float Bs[16][64];
    int t = threadIdx.x;
    int ty = t >> 3;              // 0..15
    int tx = t & 7;               // 0..7
    int m0 = blockIdx.y * 64;
    int n0 = blockIdx.x * 64;
    int kslices = (sel == 1) ? SPLITK : 1;
    int klen = K / kslices;
    int kbeg = blockIdx.z * klen;

    ull acc2[4][4];
#pragma unroll
    for (int i = 0; i < 4; i++)
#pragma unroll
        for (int j = 0; j < 4; j++) acc2[i][j] = 0ULL;

    for (int k0 = kbeg; k0 < kbeg + klen; k0 += 16) {
#pragma unroll
        for (int l = 0; l < 2; l++) {
            int lin = t + l * 128;        // 0..255
            int mm = lin & 63;
            int kk4 = lin >> 6;           // 0..3
            float4 av = *(const float4*)(A + (size_t)(m0 + mm) * K + k0 + kk4 * 4);
            As[kk4 * 4 + 0][mm] = av.x; As[kk4 * 4 + 1][mm] = av.y;
            As[kk4 * 4 + 2][mm] = av.z; As[kk4 * 4 + 3][mm] = av.w;
            float4 bv = *(const float4*)(B + (size_t)(n0 + mm) * K + k0 + kk4 * 4);
            Bs[kk4 * 4 + 0][mm] = bv.x; Bs[kk4 * 4 + 1][mm] = bv.y;
            Bs[kk4 * 4 + 2][mm] = bv.z; Bs[kk4 * 4 + 3][mm] = bv.w;
        }
        __syncthreads();
#pragma unroll
        for (int kk = 0; kk < 16; kk++) {
            float4 a = *(const float4*)&As[kk][ty * 4];
            ull ad0 = pack2(a.x, a.x), ad1 = pack2(a.y, a.y);
            ull ad2 = pack2(a.z, a.z), ad3 = pack2(a.w, a.w);
            const ull* bp = (const ull*)&Bs[kk][tx * 8];
            ull b0 = bp[0], b1 = bp[1], b2 = bp[2], b3 = bp[3];
            fma2(acc2[0][0], ad0, b0); fma2(acc2[0][1], ad0, b1);
            fma2(acc2[0][2], ad0, b2); fma2(acc2[0][3], ad0, b3);
            fma2(acc2[1][0], ad1, b0); fma2(acc2[1][1], ad1, b1);
            fma2(acc2[1][2], ad1, b2); fma2(acc2[1][3], ad1, b3);
            fma2(acc2[2][0], ad2, b0); fma2(acc2[2][1], ad2, b1);
            fma2(acc2[2][2], ad2, b2); fma2(acc2[2][3], ad2, b3);
            fma2(acc2[3][0], ad3, b0); fma2(acc2[3][1], ad3, b1);
            fma2(acc2[3][2], ad3, b2); fma2(acc2[3][3], ad3, b3);
        }
        __syncthreads();
    }

    if (sel == 1) {
#pragma unroll
        for (int i = 0; i < 4; i++) {
            int m = m0 + ty * 4 + i;
            float* cr = C + (size_t)m * N + n0 + tx * 8;
            float2 u0 = unpack2(acc2[i][0]), u1 = unpack2(acc2[i][1]);
            float2 u2 = unpack2(acc2[i][2]), u3 = unpack2(acc2[i][3]);
            redv4(cr,     u0.x, u0.y, u1.x, u1.y);
            redv4(cr + 4, u2.x, u2.y, u3.x, u3.y);
        }
    } else {
#pragma unroll
        for (int i = 0; i < 4; i++) {
            int m = m0 + ty * 4 + i;
            float* cr = C + (size_t)m * N + n0 + tx * 8;
            const float* br = bias + n0 + tx * 8;
#pragma unroll
            for (int jp = 0; jp < 4; jp++) {
                float2 u = unpack2(acc2[i][jp]);
                cr[2 * jp]     = u.x + __ldg(br + 2 * jp);
                cr[2 * jp + 1] = u.y + __ldg(br + 2 * jp + 1);
            }
        }
    }
}

// WT[k*G + j] = W[j*Hs + k]
__global__ void k_transpose(int which, const float* __restrict__ W) {
    int G  = (which == 1) ? G1 : G2;
    int Hs = (which == 1) ? H1S : H2S;
    float* WT = (which == 1) ? d_whh1T : d_whh2T;
    int idx = blockIdx.x * blockDim.x + threadIdx.x;
    if (idx >= G * Hs) return;
    int k = idx / G, j = idx % G;
    WT[idx] = W[(size_t)j * Hs + k];
}

// gates[b, j] = xw[t*NB+b, j] + sum_k h[b,k] * WT[k, j]   (f32x2, 8 batches/thread)
__global__ void k_lstm_step(int which, int t) {
    const float* xw = (which == 1) ? d_xw1 : d_xw2;
    const float* WT = (which == 1) ? d_whh1T : d_whh2T;
    const float* hs = (which == 1) ? d_h1 : d_h2;
    int G  = (which == 1) ? G1 : G2;
    int Hs = (which == 1) ? H1S : H2S;

    __shared__ __align__(16) float hl[8 * H1S];   // [k][b] transposed
    int b0 = blockIdx.y * 8;
    for (int i = threadIdx.x; i < 8 * Hs; i += blockDim.x) {
        int k = i >> 3, b = i & 7;
        hl[i] = hs[(size_t)(b0 + b) * Hs + k];
    }
    __syncthreads();

    int j = blockIdx.x * blockDim.x + threadIdx.x;
    ull acc2[4] = {0ULL, 0ULL, 0ULL, 0ULL};

    for (int k = 0; k < Hs; k++) {
        float w = __ldg(WT + (size_t)k * G + j);
        ull wd = pack2(w, w);
        const ull* hp = (const ull*)(hl + k * 8);
        fma2(acc2[0], wd, hp[0]);
        fma2(acc2[1], wd, hp[1]);
        fma2(acc2[2], wd, hp[2]);
        fma2(acc2[3], wd, hp[3]);
    }
#pragma unroll
    for (int p = 0; p < 4; p++) {
        float2 u = unpack2(acc2[p]);
        int bA = b0 + 2 * p, bB = bA + 1;
        d_gates[(size_t)bA * G + j] = u.x + __ldg(xw + ((size_t)t * NB + bA) * G + j);
        d_gates[(size_t)bB * G + j] = u.y + __ldg(xw + ((size_t)t * NB + bB) * G + j);
    }
}

// PyTorch gate order (i,f,g,o)
__global__ void k_lstm_elem(int which, int t) {
    int Hs = (which == 1) ? H1S : H2S;
    int G = 4 * Hs;
    float* hs = (which == 1) ? d_h1 : d_h2;
    float* cs = (which == 1) ? d_c1 : d_c2;
    int idx = blockIdx.x * blockDim.x + threadIdx.x;
    if (idx >= NB * Hs) return;
    int b = idx / Hs, u = idx % Hs;
    const float* gr = d_gates + (size_t)b * G;
    float iv = sigf(gr[u]);
    float fv = sigf(gr[Hs + u]);
    float gv = tanhf(gr[2 * Hs + u]);
    float ov = sigf(gr[3 * Hs + u]);
    float c = fv * cs[idx] + iv * gv;
    float h = ov * tanhf(c);
    cs[idx] = c;
    hs[idx] = h;
    if (which == 1) d_y1[(size_t)t * NB * H1S + idx] = h;
}

// out[b*2000 + j] = sum_k h2[b,k] * W_out[j,k] + b_out[j]   (f32x2 over k)
__global__ void k_out(const float* __restrict__ Wo, const float* __restrict__ bo,
                      float* __restrict__ out) {
    __shared__ __align__(16) float hr[H2S];
    int b = blockIdx.y;
    if (threadIdx.x < H2S) hr[threadIdx.x] = d_h2[(size_t)b * H2S + threadIdx.x];
    __syncthreads();
    int j = blockIdx.x * blockDim.x + threadIdx.x;
    if (j >= NN * 2) return;
    const ull* wp = (const ull*)(Wo + (size_t)j * H2S);
    const ull* hp = (const ull*)hr;
    ull accA = 0, accB = 0;
#pragma unroll 8
    for (int k = 0; k < H2S / 2; k += 2) {
        fma2(accA, hp[k], wp[k]);
        fma2(accB, hp[k + 1], wp[k + 1]);
    }
    float2 uA = unpack2(accA), uB = unpack2(accB);
    out[(size_t)b * (NN * 2) + j] = uA.x + uA.y + uB.x + uB.y + __ldg(bo + j);
}

// ---------------- launch ----------------
extern "C" void kernel_launch(void* const* d_in, const int* in_sizes, int n_in,
                              void* d_out, int out_size) {
    const float* x     = (const float*)d_in[0];
    const int*   ei    = (const int*)d_in[1];     // int32 (JAX x64 disabled)
    const float* Wg    = (const float*)d_in[2];
    const float* att_s = (const float*)d_in[3];
    const float* att_d = (const float*)d_in[4];
    const float* gbias = (const float*)d_in[5];
    const float* Wih1  = (const float*)d_in[6];
    const float* Whh1  = (const float*)d_in[7];
    const float* b1    = (const float*)d_in[8];
    const float* Wih2  = (const float*)d_in[9];
    const float* Whh2  = (const float*)d_in[10];
    const float* b2    = (const float*)d_in[11];
    const float* Wo    = (const float*)d_in[12];
    const float* bo    = (const float*)d_in[13];
    float* out = (float*)d_out;

    int E = in_sizes[1] / 2;
    if (E > EMAX) E = EMAX;
    int etot = E + NTOT;

    k_init<<<(NTOT * 48 + 255) / 256, 256>>>();
    k_gemm_h<<<(NTOT * 48 + 255) / 256, 256>>>(x, Wg);
    k_biasinit<<<(TBR * G1 + 255) / 256, 256>>>(b1);
    k_transpose<<<(H1S * G1 + 255) / 256, 256>>>(1, Whh1);
    k_transpose<<<(H2S * G2 + 255) / 256, 256>>>(2, Whh2);
    k_attn<<<(NTOT * 2 + 255) / 256, 256>>>(att_s, att_d);
    k_passA<<<(etot * 2 + 255) / 256, 256>>>(ei, E);
    k_passB<<<(etot * 2 + 255) / 256, 256>>>(ei, E);
    k_alpha<<<(etot * 2 + 255) / 256, 256>>>(ei, E);
    k_passC<<<(etot * 12 + 255) / 256, 256>>>(ei, E);
    k_reshape<<<(TBR * D1 + 255) / 256, 256>>>(gbias);

    k_sgemm<<<dim3(G1 / 64, TBR / 64, SPLITK), 128>>>(1, Wih1, b1, G1, D1);
    for (int t = 0; t < SEQL; t++) {
        k_lstm_step<<<dim3(G1 / 128, NB / 8), 128>>>(1, t);
        k_lstm_elem<<<(NB * H1S + 255) / 256, 256>>>(1, t);
    }

    k_sgemm<<<dim3(G2 / 64, TBR / 64, 1), 128>>>(2, Wih2, b2, G2, H1S);
    for (int t = 0; t < SEQL; t++) {
        k_lstm_step<<<dim3(G2 / 128, NB / 8), 128>>>(2, t);
        k_lstm_elem<<<(NB * H2S + 255) / 256, 256>>>(2, t);
    }

    k_out<<<dim3((NN * 2 + 255) / 256, NB), 256>>>(Wo, bo, out);
}